// round 2
// baseline (speedup 1.0000x reference)
#include <cuda_runtime.h>
#include <math_constants.h>
#include <cstdint>

// FilterDetection: score threshold + morphological opening (erode k=4, dilate k=4)
// on a 32x1024x1024 mask. cv2 semantics:
//   erode window offsets  dr,dc in [-2,+1], border identity +inf
//   dilate window offsets dr,dc in [-1,+2], border identity -inf
// Fused single-pass kernel: 32x32 output tile, 38x38 thresholded halo in smem,
// separable row-min -> col-min (erosion), then 4x4 max (dilation).

#define TS   32      // output tile
#define HS   38      // TS + 6 halo
#define PITCH 40     // smem pitch (avoid 32-way alignment pathologies)

__global__ void score_thresh_kernel(const float* __restrict__ s,
                                    float* __restrict__ out, int n) {
    int i = blockIdx.x * blockDim.x + threadIdx.x;
    if (i < n) {
        float v = s[i];
        out[i] = (v >= 0.5f) ? v : 0.0f;
    }
}

__global__ __launch_bounds__(1024, 2)
void open_kernel(const float* __restrict__ mask, float* __restrict__ out) {
    __shared__ float m[HS][PITCH];     // thresholded input + halo (+inf OOB)
    __shared__ float rmin[HS][PITCH];  // horizontal min (erode, col pass)
    __shared__ float er[HS][PITCH];    // eroded (-inf outside image)

    const int gr0 = blockIdx.y * TS;
    const int gc0 = blockIdx.x * TS;
    const float* img  = mask + (size_t)blockIdx.z * 1024 * 1024;
    float*       oimg = out  + (size_t)blockIdx.z * 1024 * 1024;
    const int tid = threadIdx.y * 32 + threadIdx.x;

    // Load 38x38 halo, thresholded; OOB -> +inf (erosion identity).
    for (int i = tid; i < HS * HS; i += 1024) {
        int r = i / HS, c = i % HS;
        int gr = gr0 + r - 3, gc = gc0 + c - 3;
        float v = CUDART_INF_F;
        if ((unsigned)gr < 1024u && (unsigned)gc < 1024u) {
            float x = __ldg(&img[gr * 1024 + gc]);
            v = (x >= 0.5f) ? x : 0.0f;
        }
        m[r][c] = v;
    }
    __syncthreads();

    // Horizontal erosion: rowmin[r][c] = min over dc in [-2,+1].
    // Needed cols (local): 2..36 (35 cols), all 38 rows.
    for (int i = tid; i < HS * 35; i += 1024) {
        int r = i / 35, c = 2 + (i % 35);
        float v = fminf(fminf(m[r][c - 2], m[r][c - 1]),
                        fminf(m[r][c],     m[r][c + 1]));
        rmin[r][c] = v;
    }
    __syncthreads();

    // Vertical erosion: er[r][c] = min over dr in [-2,+1].
    // Needed rows/cols (local): 2..36 (35x35). Outside the image the eroded
    // plane does not exist -> -inf (dilation identity).
    for (int i = tid; i < 35 * 35; i += 1024) {
        int r = 2 + i / 35, c = 2 + (i % 35);
        int gr = gr0 + r - 3, gc = gc0 + c - 3;
        float v = fminf(fminf(rmin[r - 2][c], rmin[r - 1][c]),
                        fminf(rmin[r][c],     rmin[r + 1][c]));
        if ((unsigned)gr >= 1024u || (unsigned)gc >= 1024u) v = -CUDART_INF_F;
        er[r][c] = v;
    }
    __syncthreads();

    // Dilation: out = max over dr,dc in [-1,+2] of eroded.
    const int r = 3 + threadIdx.y, c = 3 + threadIdx.x;
    float v = -CUDART_INF_F;
#pragma unroll
    for (int dr = -1; dr <= 2; dr++) {
#pragma unroll
        for (int dc = -1; dc <= 2; dc++) {
            v = fmaxf(v, er[r + dr][c + dc]);
        }
    }
    oimg[(size_t)(gr0 + threadIdx.y) * 1024 + (gc0 + threadIdx.x)] = v;
}

extern "C" void kernel_launch(void* const* d_in, const int* in_sizes, int n_in,
                              void* d_out, int out_size) {
    const float* score = (const float*)d_in[0];   // 32*1000
    const float* mask  = (const float*)d_in[1];   // 32*1024*1024
    float* out = (float*)d_out;

    const int n_score = in_sizes[0];              // 32000
    float* out_score = out;
    float* out_mask  = out + n_score;

    score_thresh_kernel<<<(n_score + 255) / 256, 256>>>(score, out_score, n_score);

    dim3 grid(1024 / TS, 1024 / TS, 32);
    dim3 block(32, 32);
    open_kernel<<<grid, block>>>(mask, out_mask);
}

// round 3
// speedup vs baseline: 4.1869x; 4.1869x over previous
#include <cuda_runtime.h>
#include <math_constants.h>
#include <cstdint>

// FilterDetection: score threshold + morphological opening (erode k=4 -> dilate k=4)
// cv2 semantics: erode offsets [-2,+1] (border +inf), dilate offsets [-1,+2]
// (border -inf; eroded plane outside image = -inf).
//
// Register-pipeline kernel: each WARP owns a 128-col x 64-row strip.
// Horizontal neighbors via warp shuffles, vertical windows via 4-deep register
// rings. No shared memory, no __syncthreads.

#define CHUNK  128   // columns per warp (32 lanes x float4)
#define RSTRIP 64    // output rows per warp
#define WARPS  8     // warps per CTA (each an independent strip)

__device__ __forceinline__ float thr(float v) { return (v >= 0.5f) ? v : 0.0f; }
__device__ __forceinline__ float min4f(float a, float b, float c, float d) {
    return fminf(fminf(a, b), fminf(c, d));
}
__device__ __forceinline__ float max4f(float a, float b, float c, float d) {
    return fmaxf(fmaxf(a, b), fmaxf(c, d));
}

__global__ void score_thresh_kernel(const float* __restrict__ s,
                                    float* __restrict__ out, int n) {
    int i = blockIdx.x * blockDim.x + threadIdx.x;
    if (i < n) {
        float v = s[i];
        out[i] = (v >= 0.5f) ? v : 0.0f;
    }
}

__global__ __launch_bounds__(32 * WARPS)
void open_kernel(const float* __restrict__ mask, float* __restrict__ out) {
    const int lane  = threadIdx.x;
    const int warp  = threadIdx.y;
    const int chunk = blockIdx.x;                       // 0..7
    const int c0    = chunk * CHUNK;
    const int r0    = (blockIdx.y * WARPS + warp) * RSTRIP;
    const float* img  = mask + (size_t)blockIdx.z * (1024u * 1024u);
    float*       oimg = out  + (size_t)blockIdx.z * (1024u * 1024u);
    const int col = c0 + lane * 4;

    const bool leftEdge  = (chunk == 0);
    const bool rightEdge = (chunk == 7);
    const float INF = CUDART_INF_F;

    float4 hm[4];                       // ring: horizontal-min rows
    float  hl[4], hr0[4], hr1[4];       // ring: boundary-col horizontal mins
    float4 hx[4];                       // ring: horizontal-max of eroded rows

    // t-based counter so ring indices (&3) are compile-time under unroll-4.
    // ir = r0 - 3 + t ; r0 % 4 == 0  =>  ir mod 4 == (t+1) mod 4.
#pragma unroll 4
    for (int t = 0; t < RSTRIP + 6; ++t) {
        const int ir  = r0 - 3 + t;
        const bool rok = ((unsigned)ir < 1024u);
        const float* rowp = img + (size_t)ir * 1024;

        // ---- load input row (thresholded, +inf OOB) ----
        float4 v  = make_float4(INF, INF, INF, INF);
        float4 xl = make_float4(INF, INF, INF, INF);   // lane 0: cols c0-4..c0-1
        float4 xr = make_float4(INF, INF, INF, INF);   // lane 31: cols c0+128..+131
        if (rok) {
            float4 raw = *reinterpret_cast<const float4*>(rowp + col);
            v.x = thr(raw.x); v.y = thr(raw.y); v.z = thr(raw.z); v.w = thr(raw.w);
            if (lane == 0 && !leftEdge) {
                float4 r2 = *reinterpret_cast<const float4*>(rowp + c0 - 4);
                xl.x = thr(r2.x); xl.y = thr(r2.y); xl.z = thr(r2.z); xl.w = thr(r2.w);
            }
            if (lane == 31 && !rightEdge) {
                float4 r2 = *reinterpret_cast<const float4*>(rowp + c0 + CHUNK);
                xr.x = thr(r2.x); xr.y = thr(r2.y); xr.z = thr(r2.z); xr.w = thr(r2.w);
            }
        }

        // ---- horizontal erosion (min over cols j-2..j+1) ----
        float vlz = __shfl_up_sync(0xffffffffu, v.z, 1);
        float vlw = __shfl_up_sync(0xffffffffu, v.w, 1);
        float vrx = __shfl_down_sync(0xffffffffu, v.x, 1);
        if (lane == 0)  { vlz = xl.z; vlw = xl.w; }
        if (lane == 31) { vrx = xr.x; }
        {
            float4 h;
            h.x = min4f(vlz, vlw, v.x, v.y);
            h.y = min4f(vlw, v.x, v.y, v.z);
            h.z = min4f(v.x, v.y, v.z, v.w);
            h.w = min4f(v.y, v.z, v.w, vrx);
            const int s = (t + 1) & 3;          // == ir & 3
            hm[s]  = h;
            hl[s]  = min4f(xl.y, xl.z, xl.w, v.x);   // hmin at col c0-1   (lane 0)
            hr0[s] = min4f(v.z, v.w, xr.x, xr.y);    // hmin at col c0+128 (lane 31)
            hr1[s] = min4f(v.w, xr.x, xr.y, xr.z);   // hmin at col c0+129 (lane 31)
        }

        // ---- eroded row e = ir-1 (vertical min), then horizontal dilation max ----
        if (t >= 3) {
            const int e = ir - 1;
            float4 ev; float eL, eR0, eR1;
            if ((unsigned)e < 1024u) {
                const int a = (t + 2) & 3;   // (e-2)&3
                const int b = (t + 3) & 3;   // (e-1)&3
                const int c = (t + 0) & 3;   // (e  )&3
                const int d = (t + 1) & 3;   // (e+1)&3
                ev.x = min4f(hm[a].x, hm[b].x, hm[c].x, hm[d].x);
                ev.y = min4f(hm[a].y, hm[b].y, hm[c].y, hm[d].y);
                ev.z = min4f(hm[a].z, hm[b].z, hm[c].z, hm[d].z);
                ev.w = min4f(hm[a].w, hm[b].w, hm[c].w, hm[d].w);
                eL  = leftEdge  ? -INF : min4f(hl[a],  hl[b],  hl[c],  hl[d]);
                eR0 = rightEdge ? -INF : min4f(hr0[a], hr0[b], hr0[c], hr0[d]);
                eR1 = rightEdge ? -INF : min4f(hr1[a], hr1[b], hr1[c], hr1[d]);
            } else {
                ev = make_float4(-INF, -INF, -INF, -INF);
                eL = eR0 = eR1 = -INF;
            }
            float elw = __shfl_up_sync(0xffffffffu, ev.w, 1);
            float enx = __shfl_down_sync(0xffffffffu, ev.x, 1);
            float eny = __shfl_down_sync(0xffffffffu, ev.y, 1);
            if (lane == 0)  { elw = eL; }
            if (lane == 31) { enx = eR0; eny = eR1; }
            {
                float4 g;
                g.x = max4f(elw,  ev.x, ev.y, ev.z);
                g.y = max4f(ev.x, ev.y, ev.z, ev.w);
                g.z = max4f(ev.y, ev.z, ev.w, enx);
                g.w = max4f(ev.z, ev.w, enx, eny);
                hx[t & 3] = g;                  // == e & 3
            }

            // ---- output row o = e-2 = vertical max of hx[o-1..o+2] ----
            if (t >= 6) {
                const int o = ir - 3;
                const int a = (t + 3) & 3;   // (o-1)&3
                const int b = (t + 0) & 3;   // (o  )&3
                const int c = (t + 1) & 3;   // (o+1)&3
                const int d = (t + 2) & 3;   // (o+2)&3
                float4 r;
                r.x = max4f(hx[a].x, hx[b].x, hx[c].x, hx[d].x);
                r.y = max4f(hx[a].y, hx[b].y, hx[c].y, hx[d].y);
                r.z = max4f(hx[a].z, hx[b].z, hx[c].z, hx[d].z);
                r.w = max4f(hx[a].w, hx[b].w, hx[c].w, hx[d].w);
                *reinterpret_cast<float4*>(oimg + (size_t)o * 1024 + col) = r;
            }
        }
    }
}

extern "C" void kernel_launch(void* const* d_in, const int* in_sizes, int n_in,
                              void* d_out, int out_size) {
    const float* score = (const float*)d_in[0];   // 32*1000
    const float* mask  = (const float*)d_in[1];   // 32*1024*1024
    float* out = (float*)d_out;

    const int n_score = in_sizes[0];              // 32000
    float* out_score = out;
    float* out_mask  = out + n_score;

    score_thresh_kernel<<<(n_score + 255) / 256, 256>>>(score, out_score, n_score);

    dim3 grid(1024 / CHUNK, 1024 / (RSTRIP * WARPS), 32);   // (8, 2, 32)
    dim3 block(32, WARPS);
    open_kernel<<<grid, block>>>(mask, out_mask);
}